// round 14
// baseline (speedup 1.0000x reference)
#include <cuda_runtime.h>
#include <cuda_fp16.h>
#include <cstdint>

// LocallyConnected2d via single-pass fp16 mma.sync m16n8k16 implicit GEMM.
// out[b,o,h,w] = sum_{c,k} patch(x)[b,c,h,w,k] * W[o,c,h,w,k]
// x: [128,64,32,32] f32   weight: [1,64,64,32,32,9] f32   out: [128,64,32,32] f32
//
// R14 = R12 mainloop (R13's rescheduling regressed -> reverted) with:
//  - epilogue stores DIRECTLY to out[b][o][hw] (scalar, 4KB-stride scatter;
//    adjacent-hw CTAs co-fill each 32B sector in L2 -> no DRAM amplification).
//    g_outT and the out_transpose kernel are GONE (-11 us, -64 MB traffic).
//  - prep_x reads vectorized to float4 (4x fewer LDG; it was issue-bound).

#define BATCH 128
#define CI    64
#define CO    64
#define HGT   32
#define WID   32
#define HWN   1024
#define KC    64
#define NCHUNK 9

#define ASTRH  272                  // A fp16 row stride bytes
#define BSTRH  144                  // B fp16 row stride bytes
#define OFF_BH 17408                // 64*272
#define STAGE  26624                // 17408 + 64*144
#define DYN_BYTES (2 * STAGE)

#define OSTRIDE 2359296             // 4*CI*HWN*9 floats between o and o+4

__device__ __half g_xh[CI * HGT * WID * BATCH];  // 8 MB [c][h][w][b] fp16

// ---------------- helpers ----------------------------------------------------
__device__ __forceinline__ uint32_t smem_u32(const void* p) {
    uint32_t a;
    asm("{ .reg .u64 t; cvta.to.shared.u64 t, %1; cvt.u32.u64 %0, t; }" : "=r"(a) : "l"(p));
    return a;
}
__device__ __forceinline__ void lds64(uint32_t a, uint32_t& lo, uint32_t& hi) {
    asm volatile("ld.shared.v2.b32 {%0,%1}, [%2];" : "=r"(lo), "=r"(hi) : "r"(a));
}
__device__ __forceinline__ void sts16(uint32_t a, unsigned short v) {
    asm volatile("st.shared.b16 [%0], %1;" :: "r"(a), "h"(v) : "memory");
}
__device__ __forceinline__ void cp16(uint32_t dst, const void* src, int srcbytes) {
    asm volatile("cp.async.cg.shared.global [%0], [%1], 16, %2;"
                 :: "r"(dst), "l"(src), "r"(srcbytes) : "memory");
}
#define CP_COMMIT() asm volatile("cp.async.commit_group;" ::: "memory")
#define CP_WAIT0()  asm volatile("cp.async.wait_group 0;" ::: "memory")
__device__ __forceinline__ void ldm4t(uint32_t* r, uint32_t addr) {
    asm volatile("ldmatrix.sync.aligned.m8n8.x4.trans.shared.b16 {%0,%1,%2,%3}, [%4];"
                 : "=r"(r[0]), "=r"(r[1]), "=r"(r[2]), "=r"(r[3]) : "r"(addr));
}
__device__ __forceinline__ void mma_f16(float* d, const uint32_t* a, const uint32_t* b) {
    asm volatile("mma.sync.aligned.m16n8k16.row.col.f32.f16.f16.f32 "
                 "{%0,%1,%2,%3}, {%4,%5,%6,%7}, {%8,%9}, {%0,%1,%2,%3};"
                 : "+f"(d[0]), "+f"(d[1]), "+f"(d[2]), "+f"(d[3])
                 : "r"(a[0]), "r"(a[1]), "r"(a[2]), "r"(a[3]), "r"(b[0]), "r"(b[1]));
}

// ---------------- Kernel 1: x -> g_xh[c][h][w][b] fp16 -----------------------
__global__ __launch_bounds__(256)
void prep_x_kernel(const float* __restrict__ x) {
    const int c = blockIdx.x >> 5;
    const int h = blockIdx.x & 31;
    __shared__ float tile[WID * 129];
    const int tid = threadIdx.x;
    // read: 1024 float4 (whole [b][w] plane), 4 per thread
#pragma unroll
    for (int it = 0; it < 4; it++) {
        const int idx = it * 256 + tid;
        const int b  = idx >> 3;
        const int w4 = (idx & 7) * 4;
        const float4 v = *reinterpret_cast<const float4*>(
            &x[(((size_t)b * CI + c) * HGT + h) * WID + w4]);
        tile[(w4 + 0) * 129 + b] = v.x;
        tile[(w4 + 1) * 129 + b] = v.y;
        tile[(w4 + 2) * 129 + b] = v.z;
        tile[(w4 + 3) * 129 + b] = v.w;
    }
    __syncthreads();
    __half2* dst = reinterpret_cast<__half2*>(g_xh) + ((size_t)(c * HGT + h) * WID) * 64;
#pragma unroll
    for (int it = 0; it < 8; it++) {
        const int idx = it * 256 + tid;       // 2048 half2
        const int w  = idx >> 6;
        const int b2 = idx & 63;
        const float f0 = tile[w * 129 + 2 * b2];
        const float f1 = tile[w * 129 + 2 * b2 + 1];
        dst[w * 64 + b2] = __floats2half2_rn(f0, f1);
    }
}

// ---------------- Kernel 2: main MMA GEMM ------------------------------------
__global__ __launch_bounds__(256, 2)
void lc2d_mma_kernel(const float* __restrict__ wgt, float* __restrict__ out) {
    extern __shared__ __align__(16) char dyns[];
    __shared__ int rowsAll[NCHUNK * KC];

    const uint32_t dynb = smem_u32(dyns);
    const int hw  = blockIdx.x;
    const int h   = hw >> 5;
    const int w   = hw & 31;
    const int tid = threadIdx.x;
    const int wrp = tid >> 5;
    const int lane = tid & 31;

    const int wm = (wrp & 1) * 64;          // M offset
    const int wn = ((wrp >> 1) & 1) * 32;   // N offset
    const int wk = wrp >> 2;                // K-split half (kk 0..31 vs 32..63)

    const int lm_r    = lane & 7;
    const int lm_koff = (lane & 16) ? 8 : 0;
    const int lm_moff = (lane & 8) ? 8 : 0;

    // ---- precompute kk -> x row for all chunks ---------------------------
    for (int t = tid; t < NCHUNK * KC; t += 256) {
        const int c  = t / 9;
        const int r9 = t - c * 9;
        const int p  = r9 / 3;
        const int q  = r9 - p * 3;
        const int hh = h + p - 1;
        const int ww = w + q - 1;
        rowsAll[t] = (hh < 0 || hh >= HGT || ww < 0 || ww >= WID)
                   ? -1 : ((c * HGT + hh) * WID + ww);
    }
    __syncthreads();

    float acc[4][4][4];
#pragma unroll
    for (int mf = 0; mf < 4; mf++)
#pragma unroll
        for (int nf = 0; nf < 4; nf++)
#pragma unroll
            for (int c = 0; c < 4; c++) acc[mf][nf][c] = 0.0f;

    // ---- B staging state: lane = kk (fixed), o = (tid>>6) + 4*i ----------
    const int kkB = tid & 63;
    int kB = kkB % 9;
    const float* srcB = wgt + ((size_t)(tid >> 6) * CI + kkB / 9) * (HWN * 9)
                            + (size_t)hw * 9 + kB;
    const uint32_t wiB = (uint32_t)((kkB >> 1) & 7);
    const uint32_t npB = ((wiB & 3) << 1) | (wiB >> 2);
    const uint32_t bDst = OFF_BH + (uint32_t)(tid >> 6) * BSTRH
                        + (uint32_t)((kkB >> 4) * 32 + npB * 4 + (kkB & 1) * 2);
    const int segA = tid & 15;
    const int kk0A = tid >> 4;

    float vv[8];

    auto ldgB = [&](int half) {
#pragma unroll
        for (int i = 0; i < 8; i++)
            vv[i] = srcB[(size_t)(half * 8 + i) * OSTRIDE];
    };
    auto cvtsts = [&](uint32_t sbn, int half) {
        const uint32_t base = sbn + bDst + (uint32_t)half * (8 * 4 * BSTRH);
#pragma unroll
        for (int i = 0; i < 8; i++)
            sts16(base + (uint32_t)i * (4 * BSTRH),
                  __half_as_ushort(__float2half_rn(vv[i])));
    };
    auto advB = [&]() {
        kB += 1;
        if (kB == 9) { kB = 0; srcB += (8 * HWN * 9 - 8); }
        else         {         srcB += (7 * HWN * 9 + 1); }
    };
    auto cpA = [&](int jn, uint32_t ab) {
#pragma unroll
        for (int it = 0; it < 4; it++) {
            const int kk  = kk0A + it * 16;
            const int row = rowsAll[jn * KC + kk];
            const __half* src = g_xh + (size_t)(row < 0 ? 0 : row) * BATCH + segA * 8;
            cp16(ab + (uint32_t)kk * ASTRH + (uint32_t)segA * 16, src, row < 0 ? 0 : 16);
        }
    };

    // ---- prologue: stage chunk 0 completely ------------------------------
    cpA(0, dynb);
    CP_COMMIT();
    ldgB(0); cvtsts(dynb, 0);
    ldgB(1); cvtsts(dynb, 1);
    advB();

    // ---- mainloop (R12 schedule): one top sync + trailing sync -----------
    for (int j = 0; j < NCHUNK; j++) {
        const uint32_t sb  = dynb + (uint32_t)(j & 1) * STAGE;
        const uint32_t sbn = dynb + (uint32_t)((j + 1) & 1) * STAGE;
        const bool more = (j + 1 < NCHUNK);

        CP_WAIT0();
        __syncthreads();          // A(j) + all warps' B(j) sts16 visible

        if (more) {
            cpA(j + 1, sbn);      // async A for next chunk
            CP_COMMIT();
            ldgB(0);              // B next chunk, first 8 o
        }

#pragma unroll
        for (int s = 0; s < 2; s++) {
            const int kk0 = wk * 32 + s * 16;
            const uint32_t arow = sb + (uint32_t)(kk0 + lm_koff + lm_r) * ASTRH;
            uint32_t a[4][4];
#pragma unroll
            for (int mf = 0; mf < 4; mf++)
                ldm4t(a[mf], arow + (uint32_t)(wm + mf * 16 + lm_moff) * 2);
            const uint32_t rB = sb + OFF_BH + (uint32_t)(wn + (lane >> 2)) * BSTRH
                              + (uint32_t)((kk0 >> 4) * 32) + (uint32_t)(lane & 3) * 8;
            uint32_t bfr[4][2];
#pragma unroll
            for (int nf = 0; nf < 4; nf++)
                lds64(rB + (uint32_t)nf * (8 * BSTRH), bfr[nf][0], bfr[nf][1]);
#pragma unroll
            for (int mf = 0; mf < 4; mf++)
#pragma unroll
                for (int nf = 0; nf < 4; nf++)
                    mma_f16(acc[mf][nf], a[mf], bfr[nf]);

            if (more) {
                if (s == 0) { cvtsts(sbn, 0); ldgB(1); }
                else        { cvtsts(sbn, 1); advB(); }
            }
        }
        __syncthreads();          // chunk consumed before overwrite
    }

    // ---- epilogue: K-split reduce via smem, DIRECT scatter store ---------
    float* sOut = reinterpret_cast<float*>(dyns);   // [o][b], stride 132
    if (wk == 1) {
#pragma unroll
        for (int mf = 0; mf < 4; mf++)
#pragma unroll
            for (int nf = 0; nf < 4; nf++)
#pragma unroll
                for (int c = 0; c < 4; c++) {
                    const int b = wm + mf * 16 + (lane >> 2) + ((c & 2) ? 8 : 0);
                    const int o = wn + nf * 8 + ((lane & 3) << 1) + (c & 1);
                    sOut[o * 132 + b] = acc[mf][nf][c];
                }
    }
    __syncthreads();
    if (wk == 0) {
#pragma unroll
        for (int mf = 0; mf < 4; mf++)
#pragma unroll
            for (int nf = 0; nf < 4; nf++)
#pragma unroll
                for (int c = 0; c < 4; c++) {
                    const int b = wm + mf * 16 + (lane >> 2) + ((c & 2) ? 8 : 0);
                    const int o = wn + nf * 8 + ((lane & 3) << 1) + (c & 1);
                    sOut[o * 132 + b] += acc[mf][nf][c];
                }
    }
    __syncthreads();

    // direct store: lanes = consecutive b (conflict-free LDS); adjacent-hw
    // CTAs co-fill each 32B out sector in L2.
    float* dst = out + hw;
#pragma unroll
    for (int it = 0; it < 32; it++) {
        const int idx = it * 256 + tid;       // 8192 elements
        const int b = idx & 127;
        const int o = idx >> 7;
        dst[((size_t)b * CO + o) * HWN] = sOut[o * 132 + b];
    }
}

// ---------------- launch -----------------------------------------------------
extern "C" void kernel_launch(void* const* d_in, const int* in_sizes, int n_in,
                              void* d_out, int out_size) {
    const float* x   = (const float*)d_in[0];
    const float* wgt = (const float*)d_in[1];
    float* out = (float*)d_out;
    (void)in_sizes; (void)n_in; (void)out_size;

    cudaFuncSetAttribute(lc2d_mma_kernel, cudaFuncAttributeMaxDynamicSharedMemorySize, DYN_BYTES);

    prep_x_kernel<<<CI * HGT, 256>>>(x);
    lc2d_mma_kernel<<<HWN, 256, DYN_BYTES>>>(wgt, out);
}

// round 15
// speedup vs baseline: 1.3408x; 1.3408x over previous
#include <cuda_runtime.h>
#include <cuda_fp16.h>
#include <cstdint>

// LocallyConnected2d via single-pass fp16 mma.sync m16n8k16 implicit GEMM.
// out[b,o,h,w] = sum_{c,k} patch(x)[b,c,h,w,k] * W[o,c,h,w,k]
// x: [128,64,32,32] f32   weight: [1,64,64,32,32,9] f32   out: [128,64,32,32] f32
//
// R15 = R12 mainloop + g_outT/out_transpose epilogue (R14's direct scatter
//       store regressed 92->143 us: 32 L2 lines per store warp-instr) with
//       prep_x float4-vectorized reads kept (it was issue-bound at 44%).

#define BATCH 128
#define CI    64
#define CO    64
#define HGT   32
#define WID   32
#define HWN   1024
#define KC    64
#define NCHUNK 9

#define ASTRH  272                  // A fp16 row stride bytes
#define BSTRH  144                  // B fp16 row stride bytes
#define OFF_BH 17408                // 64*272
#define STAGE  26624                // 17408 + 64*144
#define DYN_BYTES (2 * STAGE)

#define OSTRIDE 2359296             // 4*CI*HWN*9 floats between o and o+4

__device__ __half g_xh[CI * HGT * WID * BATCH];  // 8 MB  [c][h][w][b] fp16
__device__ float  g_outT[HWN * CO * BATCH];      // 32 MB [hw][o][b]

// ---------------- helpers ----------------------------------------------------
__device__ __forceinline__ uint32_t smem_u32(const void* p) {
    uint32_t a;
    asm("{ .reg .u64 t; cvta.to.shared.u64 t, %1; cvt.u32.u64 %0, t; }" : "=r"(a) : "l"(p));
    return a;
}
__device__ __forceinline__ void lds64(uint32_t a, uint32_t& lo, uint32_t& hi) {
    asm volatile("ld.shared.v2.b32 {%0,%1}, [%2];" : "=r"(lo), "=r"(hi) : "r"(a));
}
__device__ __forceinline__ void sts16(uint32_t a, unsigned short v) {
    asm volatile("st.shared.b16 [%0], %1;" :: "r"(a), "h"(v) : "memory");
}
__device__ __forceinline__ void cp16(uint32_t dst, const void* src, int srcbytes) {
    asm volatile("cp.async.cg.shared.global [%0], [%1], 16, %2;"
                 :: "r"(dst), "l"(src), "r"(srcbytes) : "memory");
}
#define CP_COMMIT() asm volatile("cp.async.commit_group;" ::: "memory")
#define CP_WAIT0()  asm volatile("cp.async.wait_group 0;" ::: "memory")
__device__ __forceinline__ void ldm4t(uint32_t* r, uint32_t addr) {
    asm volatile("ldmatrix.sync.aligned.m8n8.x4.trans.shared.b16 {%0,%1,%2,%3}, [%4];"
                 : "=r"(r[0]), "=r"(r[1]), "=r"(r[2]), "=r"(r[3]) : "r"(addr));
}
__device__ __forceinline__ void mma_f16(float* d, const uint32_t* a, const uint32_t* b) {
    asm volatile("mma.sync.aligned.m16n8k16.row.col.f32.f16.f16.f32 "
                 "{%0,%1,%2,%3}, {%4,%5,%6,%7}, {%8,%9}, {%0,%1,%2,%3};"
                 : "+f"(d[0]), "+f"(d[1]), "+f"(d[2]), "+f"(d[3])
                 : "r"(a[0]), "r"(a[1]), "r"(a[2]), "r"(a[3]), "r"(b[0]), "r"(b[1]));
}

// ---------------- Kernel 1: x -> g_xh[c][h][w][b] fp16 -----------------------
__global__ __launch_bounds__(256)
void prep_x_kernel(const float* __restrict__ x) {
    const int c = blockIdx.x >> 5;
    const int h = blockIdx.x & 31;
    __shared__ float tile[WID * 129];
    const int tid = threadIdx.x;
    // read: 1024 float4 (whole [b][w] plane), 4 per thread
#pragma unroll
    for (int it = 0; it < 4; it++) {
        const int idx = it * 256 + tid;
        const int b  = idx >> 3;
        const int w4 = (idx & 7) * 4;
        const float4 v = *reinterpret_cast<const float4*>(
            &x[(((size_t)b * CI + c) * HGT + h) * WID + w4]);
        tile[(w4 + 0) * 129 + b] = v.x;
        tile[(w4 + 1) * 129 + b] = v.y;
        tile[(w4 + 2) * 129 + b] = v.z;
        tile[(w4 + 3) * 129 + b] = v.w;
    }
    __syncthreads();
    __half2* dst = reinterpret_cast<__half2*>(g_xh) + ((size_t)(c * HGT + h) * WID) * 64;
#pragma unroll
    for (int it = 0; it < 8; it++) {
        const int idx = it * 256 + tid;       // 2048 half2
        const int w  = idx >> 6;
        const int b2 = idx & 63;
        const float f0 = tile[w * 129 + 2 * b2];
        const float f1 = tile[w * 129 + 2 * b2 + 1];
        dst[w * 64 + b2] = __floats2half2_rn(f0, f1);
    }
}

// ---------------- Kernel 2: main MMA GEMM (R12 schedule) ---------------------
__global__ __launch_bounds__(256, 2)
void lc2d_mma_kernel(const float* __restrict__ wgt) {
    extern __shared__ __align__(16) char dyns[];
    __shared__ int rowsAll[NCHUNK * KC];

    const uint32_t dynb = smem_u32(dyns);
    const int hw  = blockIdx.x;
    const int h   = hw >> 5;
    const int w   = hw & 31;
    const int tid = threadIdx.x;
    const int wrp = tid >> 5;
    const int lane = tid & 31;

    const int wm = (wrp & 1) * 64;          // M offset
    const int wn = ((wrp >> 1) & 1) * 32;   // N offset
    const int wk = wrp >> 2;                // K-split half (kk 0..31 vs 32..63)

    const int lm_r    = lane & 7;
    const int lm_koff = (lane & 16) ? 8 : 0;
    const int lm_moff = (lane & 8) ? 8 : 0;

    // ---- precompute kk -> x row for all chunks ---------------------------
    for (int t = tid; t < NCHUNK * KC; t += 256) {
        const int c  = t / 9;
        const int r9 = t - c * 9;
        const int p  = r9 / 3;
        const int q  = r9 - p * 3;
        const int hh = h + p - 1;
        const int ww = w + q - 1;
        rowsAll[t] = (hh < 0 || hh >= HGT || ww < 0 || ww >= WID)
                   ? -1 : ((c * HGT + hh) * WID + ww);
    }
    __syncthreads();

    float acc[4][4][4];
#pragma unroll
    for (int mf = 0; mf < 4; mf++)
#pragma unroll
        for (int nf = 0; nf < 4; nf++)
#pragma unroll
            for (int c = 0; c < 4; c++) acc[mf][nf][c] = 0.0f;

    // ---- B staging state: lane = kk (fixed), o = (tid>>6) + 4*i ----------
    const int kkB = tid & 63;
    int kB = kkB % 9;
    const float* srcB = wgt + ((size_t)(tid >> 6) * CI + kkB / 9) * (HWN * 9)
                            + (size_t)hw * 9 + kB;
    const uint32_t wiB = (uint32_t)((kkB >> 1) & 7);
    const uint32_t npB = ((wiB & 3) << 1) | (wiB >> 2);
    const uint32_t bDst = OFF_BH + (uint32_t)(tid >> 6) * BSTRH
                        + (uint32_t)((kkB >> 4) * 32 + npB * 4 + (kkB & 1) * 2);
    const int segA = tid & 15;
    const int kk0A = tid >> 4;

    float vv[8];

    auto ldgB = [&](int half) {
#pragma unroll
        for (int i = 0; i < 8; i++)
            vv[i] = srcB[(size_t)(half * 8 + i) * OSTRIDE];
    };
    auto cvtsts = [&](uint32_t sbn, int half) {
        const uint32_t base = sbn + bDst + (uint32_t)half * (8 * 4 * BSTRH);
#pragma unroll
        for (int i = 0; i < 8; i++)
            sts16(base + (uint32_t)i * (4 * BSTRH),
                  __half_as_ushort(__float2half_rn(vv[i])));
    };
    auto advB = [&]() {
        kB += 1;
        if (kB == 9) { kB = 0; srcB += (8 * HWN * 9 - 8); }
        else         {         srcB += (7 * HWN * 9 + 1); }
    };
    auto cpA = [&](int jn, uint32_t ab) {
#pragma unroll
        for (int it = 0; it < 4; it++) {
            const int kk  = kk0A + it * 16;
            const int row = rowsAll[jn * KC + kk];
            const __half* src = g_xh + (size_t)(row < 0 ? 0 : row) * BATCH + segA * 8;
            cp16(ab + (uint32_t)kk * ASTRH + (uint32_t)segA * 16, src, row < 0 ? 0 : 16);
        }
    };

    // ---- prologue: stage chunk 0 completely ------------------------------
    cpA(0, dynb);
    CP_COMMIT();
    ldgB(0); cvtsts(dynb, 0);
    ldgB(1); cvtsts(dynb, 1);
    advB();

    // ---- mainloop: one top sync + trailing sync (R12) --------------------
    for (int j = 0; j < NCHUNK; j++) {
        const uint32_t sb  = dynb + (uint32_t)(j & 1) * STAGE;
        const uint32_t sbn = dynb + (uint32_t)((j + 1) & 1) * STAGE;
        const bool more = (j + 1 < NCHUNK);

        CP_WAIT0();
        __syncthreads();          // A(j) + all warps' B(j) sts16 visible

        if (more) {
            cpA(j + 1, sbn);      // async A for next chunk
            CP_COMMIT();
            ldgB(0);              // B next chunk, first 8 o
        }

#pragma unroll
        for (int s = 0; s < 2; s++) {
            const int kk0 = wk * 32 + s * 16;
            const uint32_t arow = sb + (uint32_t)(kk0 + lm_koff + lm_r) * ASTRH;
            uint32_t a[4][4];
#pragma unroll
            for (int mf = 0; mf < 4; mf++)
                ldm4t(a[mf], arow + (uint32_t)(wm + mf * 16 + lm_moff) * 2);
            const uint32_t rB = sb + OFF_BH + (uint32_t)(wn + (lane >> 2)) * BSTRH
                              + (uint32_t)((kk0 >> 4) * 32) + (uint32_t)(lane & 3) * 8;
            uint32_t bfr[4][2];
#pragma unroll
            for (int nf = 0; nf < 4; nf++)
                lds64(rB + (uint32_t)nf * (8 * BSTRH), bfr[nf][0], bfr[nf][1]);
#pragma unroll
            for (int mf = 0; mf < 4; mf++)
#pragma unroll
                for (int nf = 0; nf < 4; nf++)
                    mma_f16(acc[mf][nf], a[mf], bfr[nf]);

            if (more) {
                if (s == 0) { cvtsts(sbn, 0); ldgB(1); }
                else        { cvtsts(sbn, 1); advB(); }
            }
        }
        __syncthreads();          // chunk consumed before overwrite
    }

    // ---- epilogue: K-split reduce via smem, coalesced store to g_outT ----
    float* sOut = reinterpret_cast<float*>(dyns);   // [o][b], stride 132
    if (wk == 1) {
#pragma unroll
        for (int mf = 0; mf < 4; mf++)
#pragma unroll
            for (int nf = 0; nf < 4; nf++)
#pragma unroll
                for (int c = 0; c < 4; c++) {
                    const int b = wm + mf * 16 + (lane >> 2) + ((c & 2) ? 8 : 0);
                    const int o = wn + nf * 8 + ((lane & 3) << 1) + (c & 1);
                    sOut[o * 132 + b] = acc[mf][nf][c];
                }
    }
    __syncthreads();
    if (wk == 0) {
#pragma unroll
        for (int mf = 0; mf < 4; mf++)
#pragma unroll
            for (int nf = 0; nf < 4; nf++)
#pragma unroll
                for (int c = 0; c < 4; c++) {
                    const int b = wm + mf * 16 + (lane >> 2) + ((c & 2) ? 8 : 0);
                    const int o = wn + nf * 8 + ((lane & 3) << 1) + (c & 1);
                    sOut[o * 132 + b] += acc[mf][nf][c];
                }
    }
    __syncthreads();

    float* dst = g_outT + (size_t)hw * (CO * BATCH);
#pragma unroll
    for (int it = 0; it < 8; it++) {
        const int idx = it * 256 + tid;       // 2048 float4
        const int o  = idx >> 5;
        const int b4 = (idx & 31) << 2;
        const float4 v = *reinterpret_cast<const float4*>(sOut + o * 132 + b4);
        *reinterpret_cast<float4*>(dst + o * BATCH + b4) = v;
    }
}

// ---------------- Kernel 3: g_outT[hw][o][b] -> out[b][o][hw] ----------------
__global__ __launch_bounds__(256)
void out_transpose_kernel(float* __restrict__ out) {
    const int o   = blockIdx.x >> 5;
    const int hw0 = (blockIdx.x & 31) * 32;
    __shared__ float tile[BATCH * 33];
    const int tid = threadIdx.x;
#pragma unroll
    for (int it = 0; it < 16; it++) {
        const int idx = it * 256 + tid;
        const int i = idx >> 7, b = idx & 127;
        tile[b * 33 + i] = g_outT[((size_t)(hw0 + i) * CO + o) * BATCH + b];
    }
    __syncthreads();
#pragma unroll
    for (int it = 0; it < 16; it++) {
        const int idx = it * 256 + tid;
        const int b = idx >> 5, i = idx & 31;
        out[((size_t)b * CO + o) * HWN + hw0 + i] = tile[b * 33 + i];
    }
}

// ---------------- launch -----------------------------------------------------
extern "C" void kernel_launch(void* const* d_in, const int* in_sizes, int n_in,
                              void* d_out, int out_size) {
    const float* x   = (const float*)d_in[0];
    const float* wgt = (const float*)d_in[1];
    float* out = (float*)d_out;
    (void)in_sizes; (void)n_in; (void)out_size;

    cudaFuncSetAttribute(lc2d_mma_kernel, cudaFuncAttributeMaxDynamicSharedMemorySize, DYN_BYTES);

    prep_x_kernel<<<CI * HGT, 256>>>(x);
    lc2d_mma_kernel<<<HWN, 256, DYN_BYTES>>>(wgt);
    out_transpose_kernel<<<CO * 32, 256>>>(out);
}

// round 16
// speedup vs baseline: 1.3548x; 1.0104x over previous
#include <cuda_runtime.h>
#include <cuda_fp16.h>
#include <cstdint>

// LocallyConnected2d via single-pass fp16 mma.sync m16n8k16 implicit GEMM.
// out[b,o,h,w] = sum_{c,k} patch(x)[b,c,h,w,k] * W[o,c,h,w,k]
// x: [128,64,32,32] f32   weight: [1,64,64,32,32,9] f32   out: [128,64,32,32] f32
//
// R16 = R15 with the redundant trailing per-chunk __syncthreads removed.
// Ordering proof: buffer(j+1)==buffer(j-1); its last readers (compute j-1)
// all finished before iteration j's TOP barrier, so the top barrier alone
// orders every cross-warp smem dependency. One sync added before epilogue
// smem reuse. (R13 removed this barrier too but bundled it with staging
// rescheduling that regressed; this isolates the barrier change.)

#define BATCH 128
#define CI    64
#define CO    64
#define HGT   32
#define WID   32
#define HWN   1024
#define KC    64
#define NCHUNK 9

#define ASTRH  272                  // A fp16 row stride bytes
#define BSTRH  144                  // B fp16 row stride bytes
#define OFF_BH 17408                // 64*272
#define STAGE  26624                // 17408 + 64*144
#define DYN_BYTES (2 * STAGE)

#define OSTRIDE 2359296             // 4*CI*HWN*9 floats between o and o+4

__device__ __half g_xh[CI * HGT * WID * BATCH];  // 8 MB  [c][h][w][b] fp16
__device__ float  g_outT[HWN * CO * BATCH];      // 32 MB [hw][o][b]

// ---------------- helpers ----------------------------------------------------
__device__ __forceinline__ uint32_t smem_u32(const void* p) {
    uint32_t a;
    asm("{ .reg .u64 t; cvta.to.shared.u64 t, %1; cvt.u32.u64 %0, t; }" : "=r"(a) : "l"(p));
    return a;
}
__device__ __forceinline__ void lds64(uint32_t a, uint32_t& lo, uint32_t& hi) {
    asm volatile("ld.shared.v2.b32 {%0,%1}, [%2];" : "=r"(lo), "=r"(hi) : "r"(a));
}
__device__ __forceinline__ void sts16(uint32_t a, unsigned short v) {
    asm volatile("st.shared.b16 [%0], %1;" :: "r"(a), "h"(v) : "memory");
}
__device__ __forceinline__ void cp16(uint32_t dst, const void* src, int srcbytes) {
    asm volatile("cp.async.cg.shared.global [%0], [%1], 16, %2;"
                 :: "r"(dst), "l"(src), "r"(srcbytes) : "memory");
}
#define CP_COMMIT() asm volatile("cp.async.commit_group;" ::: "memory")
#define CP_WAIT0()  asm volatile("cp.async.wait_group 0;" ::: "memory")
__device__ __forceinline__ void ldm4t(uint32_t* r, uint32_t addr) {
    asm volatile("ldmatrix.sync.aligned.m8n8.x4.trans.shared.b16 {%0,%1,%2,%3}, [%4];"
                 : "=r"(r[0]), "=r"(r[1]), "=r"(r[2]), "=r"(r[3]) : "r"(addr));
}
__device__ __forceinline__ void mma_f16(float* d, const uint32_t* a, const uint32_t* b) {
    asm volatile("mma.sync.aligned.m16n8k16.row.col.f32.f16.f16.f32 "
                 "{%0,%1,%2,%3}, {%4,%5,%6,%7}, {%8,%9}, {%0,%1,%2,%3};"
                 : "+f"(d[0]), "+f"(d[1]), "+f"(d[2]), "+f"(d[3])
                 : "r"(a[0]), "r"(a[1]), "r"(a[2]), "r"(a[3]), "r"(b[0]), "r"(b[1]));
}

// ---------------- Kernel 1: x -> g_xh[c][h][w][b] fp16 -----------------------
__global__ __launch_bounds__(256)
void prep_x_kernel(const float* __restrict__ x) {
    const int c = blockIdx.x >> 5;
    const int h = blockIdx.x & 31;
    __shared__ float tile[WID * 129];
    const int tid = threadIdx.x;
#pragma unroll
    for (int it = 0; it < 4; it++) {
        const int idx = it * 256 + tid;
        const int b  = idx >> 3;
        const int w4 = (idx & 7) * 4;
        const float4 v = *reinterpret_cast<const float4*>(
            &x[(((size_t)b * CI + c) * HGT + h) * WID + w4]);
        tile[(w4 + 0) * 129 + b] = v.x;
        tile[(w4 + 1) * 129 + b] = v.y;
        tile[(w4 + 2) * 129 + b] = v.z;
        tile[(w4 + 3) * 129 + b] = v.w;
    }
    __syncthreads();
    __half2* dst = reinterpret_cast<__half2*>(g_xh) + ((size_t)(c * HGT + h) * WID) * 64;
#pragma unroll
    for (int it = 0; it < 8; it++) {
        const int idx = it * 256 + tid;       // 2048 half2
        const int w  = idx >> 6;
        const int b2 = idx & 63;
        const float f0 = tile[w * 129 + 2 * b2];
        const float f1 = tile[w * 129 + 2 * b2 + 1];
        dst[w * 64 + b2] = __floats2half2_rn(f0, f1);
    }
}

// ---------------- Kernel 2: main MMA GEMM ------------------------------------
__global__ __launch_bounds__(256, 2)
void lc2d_mma_kernel(const float* __restrict__ wgt) {
    extern __shared__ __align__(16) char dyns[];
    __shared__ int rowsAll[NCHUNK * KC];

    const uint32_t dynb = smem_u32(dyns);
    const int hw  = blockIdx.x;
    const int h   = hw >> 5;
    const int w   = hw & 31;
    const int tid = threadIdx.x;
    const int wrp = tid >> 5;
    const int lane = tid & 31;

    const int wm = (wrp & 1) * 64;          // M offset
    const int wn = ((wrp >> 1) & 1) * 32;   // N offset
    const int wk = wrp >> 2;                // K-split half (kk 0..31 vs 32..63)

    const int lm_r    = lane & 7;
    const int lm_koff = (lane & 16) ? 8 : 0;
    const int lm_moff = (lane & 8) ? 8 : 0;

    // ---- precompute kk -> x row for all chunks ---------------------------
    for (int t = tid; t < NCHUNK * KC; t += 256) {
        const int c  = t / 9;
        const int r9 = t - c * 9;
        const int p  = r9 / 3;
        const int q  = r9 - p * 3;
        const int hh = h + p - 1;
        const int ww = w + q - 1;
        rowsAll[t] = (hh < 0 || hh >= HGT || ww < 0 || ww >= WID)
                   ? -1 : ((c * HGT + hh) * WID + ww);
    }
    __syncthreads();

    float acc[4][4][4];
#pragma unroll
    for (int mf = 0; mf < 4; mf++)
#pragma unroll
        for (int nf = 0; nf < 4; nf++)
#pragma unroll
            for (int c = 0; c < 4; c++) acc[mf][nf][c] = 0.0f;

    // ---- B staging state: lane = kk (fixed), o = (tid>>6) + 4*i ----------
    const int kkB = tid & 63;
    int kB = kkB % 9;
    const float* srcB = wgt + ((size_t)(tid >> 6) * CI + kkB / 9) * (HWN * 9)
                            + (size_t)hw * 9 + kB;
    const uint32_t wiB = (uint32_t)((kkB >> 1) & 7);
    const uint32_t npB = ((wiB & 3) << 1) | (wiB >> 2);
    const uint32_t bDst = OFF_BH + (uint32_t)(tid >> 6) * BSTRH
                        + (uint32_t)((kkB >> 4) * 32 + npB * 4 + (kkB & 1) * 2);
    const int segA = tid & 15;
    const int kk0A = tid >> 4;

    float vv[8];

    auto ldgB = [&](int half) {
#pragma unroll
        for (int i = 0; i < 8; i++)
            vv[i] = srcB[(size_t)(half * 8 + i) * OSTRIDE];
    };
    auto cvtsts = [&](uint32_t sbn, int half) {
        const uint32_t base = sbn + bDst + (uint32_t)half * (8 * 4 * BSTRH);
#pragma unroll
        for (int i = 0; i < 8; i++)
            sts16(base + (uint32_t)i * (4 * BSTRH),
                  __half_as_ushort(__float2half_rn(vv[i])));
    };
    auto advB = [&]() {
        kB += 1;
        if (kB == 9) { kB = 0; srcB += (8 * HWN * 9 - 8); }
        else         {         srcB += (7 * HWN * 9 + 1); }
    };
    auto cpA = [&](int jn, uint32_t ab) {
#pragma unroll
        for (int it = 0; it < 4; it++) {
            const int kk  = kk0A + it * 16;
            const int row = rowsAll[jn * KC + kk];
            const __half* src = g_xh + (size_t)(row < 0 ? 0 : row) * BATCH + segA * 8;
            cp16(ab + (uint32_t)kk * ASTRH + (uint32_t)segA * 16, src, row < 0 ? 0 : 16);
        }
    };

    // ---- prologue: stage chunk 0 completely ------------------------------
    cpA(0, dynb);
    CP_COMMIT();
    ldgB(0); cvtsts(dynb, 0);
    ldgB(1); cvtsts(dynb, 1);
    advB();

    // ---- mainloop: ONE barrier per chunk (top) ---------------------------
    for (int j = 0; j < NCHUNK; j++) {
        const uint32_t sb  = dynb + (uint32_t)(j & 1) * STAGE;
        const uint32_t sbn = dynb + (uint32_t)((j + 1) & 1) * STAGE;
        const bool more = (j + 1 < NCHUNK);

        CP_WAIT0();
        __syncthreads();          // A(j) + all warps' B(j) sts16 visible;
                                  // also: all warps finished compute(j-1),
                                  // so buffer(j+1)==(j-1) is free to overwrite

        if (more) {
            cpA(j + 1, sbn);      // async A for next chunk
            CP_COMMIT();
            ldgB(0);              // B next chunk, first 8 o
        }

#pragma unroll
        for (int s = 0; s < 2; s++) {
            const int kk0 = wk * 32 + s * 16;
            const uint32_t arow = sb + (uint32_t)(kk0 + lm_koff + lm_r) * ASTRH;
            uint32_t a[4][4];
#pragma unroll
            for (int mf = 0; mf < 4; mf++)
                ldm4t(a[mf], arow + (uint32_t)(wm + mf * 16 + lm_moff) * 2);
            const uint32_t rB = sb + OFF_BH + (uint32_t)(wn + (lane >> 2)) * BSTRH
                              + (uint32_t)((kk0 >> 4) * 32) + (uint32_t)(lane & 3) * 8;
            uint32_t bfr[4][2];
#pragma unroll
            for (int nf = 0; nf < 4; nf++)
                lds64(rB + (uint32_t)nf * (8 * BSTRH), bfr[nf][0], bfr[nf][1]);
#pragma unroll
            for (int mf = 0; mf < 4; mf++)
#pragma unroll
                for (int nf = 0; nf < 4; nf++)
                    mma_f16(acc[mf][nf], a[mf], bfr[nf]);

            if (more) {
                if (s == 0) { cvtsts(sbn, 0); ldgB(1); }
                else        { cvtsts(sbn, 1); advB(); }
            }
        }
        // no trailing barrier: next iteration's top sync provides ordering
    }

    // ---- epilogue: K-split reduce via smem, coalesced store to g_outT ----
    __syncthreads();              // all warps done computing before smem reuse
    float* sOut = reinterpret_cast<float*>(dyns);   // [o][b], stride 132
    if (wk == 1) {
#pragma unroll
        for (int mf = 0; mf < 4; mf++)
#pragma unroll
            for (int nf = 0; nf < 4; nf++)
#pragma unroll
                for (int c = 0; c < 4; c++) {
                    const int b = wm + mf * 16 + (lane >> 2) + ((c & 2) ? 8 : 0);
                    const int o = wn + nf * 8 + ((lane & 3) << 1) + (c & 1);
                    sOut[o * 132 + b] = acc[mf][nf][c];
                }
    }
    __syncthreads();
    if (wk == 0) {
#pragma unroll
        for (int mf = 0; mf < 4; mf++)
#pragma unroll
            for (int nf = 0; nf < 4; nf++)
#pragma unroll
                for (int c = 0; c < 4; c++) {
                    const int b = wm + mf * 16 + (lane >> 2) + ((c & 2) ? 8 : 0);
                    const int o = wn + nf * 8 + ((lane & 3) << 1) + (c & 1);
                    sOut[o * 132 + b] += acc[mf][nf][c];
                }
    }
    __syncthreads();

    float* dst = g_outT + (size_t)hw * (CO * BATCH);
#pragma unroll
    for (int it = 0; it < 8; it++) {
        const int idx = it * 256 + tid;       // 2048 float4
        const int o  = idx >> 5;
        const int b4 = (idx & 31) << 2;
        const float4 v = *reinterpret_cast<const float4*>(sOut + o * 132 + b4);
        *reinterpret_cast<float4*>(dst + o * BATCH + b4) = v;
    }
}

// ---------------- Kernel 3: g_outT[hw][o][b] -> out[b][o][hw] ----------------
__global__ __launch_bounds__(256)
void out_transpose_kernel(float* __restrict__ out) {
    const int o   = blockIdx.x >> 5;
    const int hw0 = (blockIdx.x & 31) * 32;
    __shared__ float tile[BATCH * 33];
    const int tid = threadIdx.x;
#pragma unroll
    for (int it = 0; it < 16; it++) {
        const int idx = it * 256 + tid;
        const int i = idx >> 7, b = idx & 127;
        tile[b * 33 + i] = g_outT[((size_t)(hw0 + i) * CO + o) * BATCH + b];
    }
    __syncthreads();
#pragma unroll
    for (int it = 0; it < 16; it++) {
        const int idx = it * 256 + tid;
        const int b = idx >> 5, i = idx & 31;
        out[((size_t)b * CO + o) * HWN + hw0 + i] = tile[b * 33 + i];
    }
}

// ---------------- launch -----------------------------------------------------
extern "C" void kernel_launch(void* const* d_in, const int* in_sizes, int n_in,
                              void* d_out, int out_size) {
    const float* x   = (const float*)d_in[0];
    const float* wgt = (const float*)d_in[1];
    float* out = (float*)d_out;
    (void)in_sizes; (void)n_in; (void)out_size;

    cudaFuncSetAttribute(lc2d_mma_kernel, cudaFuncAttributeMaxDynamicSharedMemorySize, DYN_BYTES);

    prep_x_kernel<<<CI * HGT, 256>>>(x);
    lc2d_mma_kernel<<<HWN, 256, DYN_BYTES>>>(wgt);
    out_transpose_kernel<<<CO * 32, 256>>>(out);
}